// round 11
// baseline (speedup 1.0000x reference)
#include <cuda_runtime.h>
#include <math.h>
#include <stdint.h>

#define NN 100000
#define EE 1600000
#define GG 64

// ---------------- scratch (device globals; no allocation allowed) ----------
__device__ float    g_h[NN * 128];
__device__ uint32_t g_hb[NN * 64];      // bf16x2 shadow of g_h (gather source)
__device__ float    g_agg[NN * 128];
__device__ float    g_z[NN * 256];
__device__ double   g_sum[256];
__device__ double   g_sumsq[256];
__device__ float    g_scale[256];
__device__ float    g_shift[256];
__device__ float    g_pool[2 * GG * 128];
__device__ float    g_cnt[2 * GG];
__device__ float    g_fc1o[GG * 256];
__device__ float    g_fc2o[GG * 64];
// preconverted weights, [n][k] bf16 (uint16), refreshed per branch
__device__ uint16_t g_eB[128 * 1024];          // embW: n=128, k=1024
__device__ uint16_t g_w1B[4 * 256 * 128];      // W1[i]: n=256, k=128
__device__ uint16_t g_w2B[4 * 128 * 256];      // W2[i]: n=128, k=256

// ---------------- helpers ---------------------------------------------------
__device__ __forceinline__ uint32_t cvt2(float e0, float e1) {
    uint32_t p;
    asm("cvt.rn.bf16x2.f32 %0, %1, %2;" : "=r"(p) : "f"(e1), "f"(e0));
    return p;
}

__device__ __forceinline__ void mma16816(float* c, const uint32_t* a, const uint32_t* b) {
    asm volatile("mma.sync.aligned.m16n8k16.row.col.f32.bf16.bf16.f32 "
                 "{%0,%1,%2,%3}, {%4,%5,%6,%7}, {%8,%9}, {%0,%1,%2,%3};"
                 : "+f"(c[0]), "+f"(c[1]), "+f"(c[2]), "+f"(c[3])
                 : "r"(a[0]), "r"(a[1]), "r"(a[2]), "r"(a[3]), "r"(b[0]), "r"(b[1]));
}

// ---------------- weight pre-conversion ------------------------------------
// src W is [K][Nn] fp32 (layer = blockIdx.y); dst H is [Nn][K] bf16
__global__ void convB_kernel(const float* __restrict__ W, uint16_t* __restrict__ H,
                             int K, int Nn) {
    const float* src = W + (size_t)blockIdx.y * K * Nn;
    uint32_t* dh = reinterpret_cast<uint32_t*>(H) + (size_t)blockIdx.y * (K * Nn / 2);
    int idx = blockIdx.x * 256 + threadIdx.x;          // over (K/2)*Nn
    if (idx >= (K / 2) * Nn) return;
    int k2 = idx / Nn, n = idx - k2 * Nn;
    float e0 = __ldg(&src[(size_t)(2 * k2) * Nn + n]);
    float e1 = __ldg(&src[(size_t)(2 * k2 + 1) * Nn + n]);
    dh[(size_t)n * (K / 2) + k2] = cvt2(e0, e1);
}

// ---------------- bf16 mma.sync GEMM: preconv B, ping-pong smem, 1 sync ------
// MODE 0: g_h[N,128] = Aext[N,1024] @ B + bias                      (+ g_hb)
// MODE 1: g_z[N,256] = (g_agg + (1+eps)*g_h)[N,128] @ B + bias
//          (grid.y = 2; accumulates BN sum/sumsq into g_sum/g_sumsq)
// MODE 2: g_h[N,128] = relu(relu(BN(g_z))[N,256] @ B + bias + g_h)  (+ g_hb)
#define AS 40   // smem row stride in bf16 elems (80 B)

template <int MODE>
__global__ __launch_bounds__(256, 2)
void mma_gemm(const float* __restrict__ Aext, const uint16_t* __restrict__ BH,
              const float* __restrict__ bias, const float* __restrict__ epsp)
{
    constexpr int K   = (MODE == 0) ? 1024 : ((MODE == 1) ? 128 : 256);
    constexpr int LDC = (MODE == 1) ? 256 : 128;
    constexpr int NCHUNK = K / 32;
    const float* A = (MODE == 0) ? Aext : ((MODE == 1) ? g_agg : g_z);
    float* C = (MODE == 1) ? g_z : g_h;

    __shared__ __align__(16) uint16_t Abuf[2][128 * AS];
    __shared__ __align__(16) uint16_t Bbuf[2][128 * AS];
    __shared__ float s_sum[128], s_sumsq[128];

    const int tid  = threadIdx.x;
    const int lane = tid & 31, wid = tid >> 5;
    const int bm = blockIdx.x * 128;
    const int bn = blockIdx.y * 128;
    const int wm = (wid >> 1) * 32;
    const int wn = (wid & 1) * 64;
    const int grp = lane >> 2, qid = lane & 3;

    if (MODE == 1 && tid < 128) { s_sum[tid] = 0.f; s_sumsq[tid] = 0.f; }
    const float ee = (MODE == 1) ? (1.0f + __ldg(epsp)) : 0.0f;

    float acc[2][8][4];
#pragma unroll
    for (int mt = 0; mt < 2; mt++)
#pragma unroll
        for (int nt = 0; nt < 8; nt++)
#pragma unroll
            for (int q = 0; q < 4; q++) acc[mt][nt][q] = 0.f;

    const int arow = tid >> 1, ahalf = tid & 1;        // A loader: row, 16-col half
    const int bnid = tid & 127, bkh = (tid >> 7) * 16; // B loader: n col, 16-k half
    const int rA = bm + arow;

    auto loadA = [&](int k0, float* v) {
        if (rA < NN) {
            const float* ap = A + (size_t)rA * K + k0 + ahalf * 16;
#pragma unroll
            for (int q = 0; q < 4; q++)
                *reinterpret_cast<float4*>(v + 4 * q) =
                    __ldg(reinterpret_cast<const float4*>(ap + 4 * q));
            if (MODE == 1) {
                const float* hp = g_h + (size_t)rA * 128 + k0 + ahalf * 16;
#pragma unroll
                for (int q = 0; q < 4; q++) {
                    float4 hv = __ldg(reinterpret_cast<const float4*>(hp + 4 * q));
                    v[4 * q + 0] = fmaf(ee, hv.x, v[4 * q + 0]);
                    v[4 * q + 1] = fmaf(ee, hv.y, v[4 * q + 1]);
                    v[4 * q + 2] = fmaf(ee, hv.z, v[4 * q + 2]);
                    v[4 * q + 3] = fmaf(ee, hv.w, v[4 * q + 3]);
                }
            }
        } else {
#pragma unroll
            for (int j = 0; j < 16; j++) v[j] = 0.f;
        }
        if (MODE == 2) {
            const int kb = k0 + ahalf * 16;
#pragma unroll
            for (int j = 0; j < 16; j++)
                v[j] = fmaxf(fmaf(v[j], g_scale[kb + j], g_shift[kb + j]), 0.f);
        }
    };
    auto loadB = [&](int k0, uint32_t* vb) {   // 16 bf16 = 8 uint32, preconverted
        const uint32_t* ph = reinterpret_cast<const uint32_t*>(BH) +
                             ((size_t)(bn + bnid) * K + k0 + bkh) / 2;
        *reinterpret_cast<uint4*>(vb)     = __ldg(reinterpret_cast<const uint4*>(ph));
        *reinterpret_cast<uint4*>(vb + 4) = __ldg(reinterpret_cast<const uint4*>(ph + 4));
    };
    auto storeA = [&](uint16_t* buf, const float* v) {
#pragma unroll
        for (int q = 0; q < 2; q++) {
            uint32_t hs[4];
#pragma unroll
            for (int p = 0; p < 4; p++)
                hs[p] = cvt2(v[q * 8 + p * 2], v[q * 8 + p * 2 + 1]);
            const int c = ahalf * 16 + q * 8;
            *reinterpret_cast<uint4*>(&buf[arow * AS + c]) = make_uint4(hs[0], hs[1], hs[2], hs[3]);
        }
    };
    auto storeB = [&](uint16_t* buf, const uint32_t* vb) {
        *reinterpret_cast<uint4*>(&buf[bnid * AS + bkh])     = *reinterpret_cast<const uint4*>(vb);
        *reinterpret_cast<uint4*>(&buf[bnid * AS + bkh + 8]) = *reinterpret_cast<const uint4*>(vb + 4);
    };
    auto mmaStep = [&](int pb) {
        const uint16_t* Ab = Abuf[pb];
        const uint16_t* Bb = Bbuf[pb];
#pragma unroll
        for (int s = 0; s < 32; s += 16) {
            uint32_t ah[2][4];
#pragma unroll
            for (int mt = 0; mt < 2; mt++) {
                const int r0 = (wm + mt * 16 + grp) * AS + s + qid * 2;
                const int r8 = r0 + 8 * AS;
                ah[mt][0] = *reinterpret_cast<const uint32_t*>(&Ab[r0]);
                ah[mt][1] = *reinterpret_cast<const uint32_t*>(&Ab[r8]);
                ah[mt][2] = *reinterpret_cast<const uint32_t*>(&Ab[r0 + 8]);
                ah[mt][3] = *reinterpret_cast<const uint32_t*>(&Ab[r8 + 8]);
            }
#pragma unroll
            for (int nt = 0; nt < 8; nt++) {
                const int nb = (wn + nt * 8 + grp) * AS + s + qid * 2;
                uint32_t bh[2];
                bh[0] = *reinterpret_cast<const uint32_t*>(&Bb[nb]);
                bh[1] = *reinterpret_cast<const uint32_t*>(&Bb[nb + 8]);
#pragma unroll
                for (int mt = 0; mt < 2; mt++)
                    mma16816(acc[mt][nt], ah[mt], bh);
            }
        }
    };

    // ---- prologue: chunk 0 ----
    {
        float va[16]; uint32_t vb[8];
        loadA(0, va); loadB(0, vb);
        storeA(Abuf[0], va); storeB(Bbuf[0], vb);
    }
    __syncthreads();

    // ---- pipelined main loop: ping-pong buffers, ONE sync per chunk ----
    for (int ch = 0; ch < NCHUNK; ch++) {
        float wa[16]; uint32_t wb[8];
        const bool more = (ch + 1 < NCHUNK);
        if (more) { loadA((ch + 1) * 32, wa); loadB((ch + 1) * 32, wb); }
        mmaStep(ch & 1);
        if (more) {
            storeA(Abuf[(ch + 1) & 1], wa);
            storeB(Bbuf[(ch + 1) & 1], wb);
            __syncthreads();
        }
    }

    // ---- epilogue (fused bias / residual / ReLU / bf16 shadow / BN stats) ----
#pragma unroll
    for (int nt = 0; nt < 8; nt++) {
        const int ccl = wn + nt * 8 + qid * 2;
        const int cc  = bn + ccl;
        const float b0 = bias[cc], b1 = bias[cc + 1];
        float cs0 = 0.f, cs1 = 0.f, cq0 = 0.f, cq1 = 0.f;
#pragma unroll
        for (int mt = 0; mt < 2; mt++) {
            const int r0 = bm + wm + mt * 16 + grp;
#pragma unroll
            for (int hrow = 0; hrow < 2; hrow++) {
                const int r = r0 + hrow * 8;
                if (r < NN) {
                    float2 o;
                    o.x = acc[mt][nt][hrow * 2 + 0] + b0;
                    o.y = acc[mt][nt][hrow * 2 + 1] + b1;
                    if (MODE == 2) {
                        const float2 h = *reinterpret_cast<const float2*>(&g_h[(size_t)r * 128 + cc]);
                        o.x = fmaxf(o.x + h.x, 0.f);
                        o.y = fmaxf(o.y + h.y, 0.f);
                    }
                    *reinterpret_cast<float2*>(&C[(size_t)r * LDC + cc]) = o;
                    if (MODE == 0 || MODE == 2)
                        g_hb[((size_t)r * 128 + cc) >> 1] = cvt2(o.x, o.y);
                    if (MODE == 1) {
                        cs0 += o.x; cq0 = fmaf(o.x, o.x, cq0);
                        cs1 += o.y; cq1 = fmaf(o.y, o.y, cq1);
                    }
                }
            }
        }
        if (MODE == 1) {
            atomicAdd(&s_sum[ccl],       cs0);
            atomicAdd(&s_sum[ccl + 1],   cs1);
            atomicAdd(&s_sumsq[ccl],     cq0);
            atomicAdd(&s_sumsq[ccl + 1], cq1);
        }
    }
    if (MODE == 1) {
        __syncthreads();
        if (tid < 128) {
            atomicAdd(&g_sum[bn + tid],   (double)s_sum[tid]);
            atomicAdd(&g_sumsq[bn + tid], (double)s_sumsq[tid]);
        }
    }
}

// ---------------- small utility kernels -----------------------------------
__global__ void zero_pool_kernel() {
    int i = blockIdx.x * 256 + threadIdx.x;
    g_pool[i] = 0.f;
    if (i < 2 * GG) g_cnt[i] = 0.f;
}

// warp per edge: gather bf16 row (256B), vector-reduce fp32 into agg[dst];
// block 0 zeroes the BN accumulators for the upcoming MODE1.
__global__ void scatter_kernel(const int* __restrict__ ei) {
    int idx = blockIdx.x * 256 + threadIdx.x;  // 200000 x 256 (== E*32)
    if (blockIdx.x == 0) { g_sum[threadIdx.x] = 0.0; g_sumsq[threadIdx.x] = 0.0; }
    int e = idx >> 5;
    int c = idx & 31;
    int src = __ldg(&ei[e]);
    int dst = __ldg(&ei[EE + e]);
    uint2 v = *reinterpret_cast<const uint2*>(&g_hb[src * 64 + c * 2]);
    float f0 = __uint_as_float(v.x << 16);
    float f1 = __uint_as_float(v.x & 0xFFFF0000u);
    float f2 = __uint_as_float(v.y << 16);
    float f3 = __uint_as_float(v.y & 0xFFFF0000u);
    float* p = &g_agg[dst * 128 + c * 4];
    asm volatile("red.global.add.v4.f32 [%0], {%1,%2,%3,%4};"
                 :: "l"(p), "f"(f0), "f"(f1), "f"(f2), "f"(f3) : "memory");
}

__global__ void bn_finalize_kernel(const float* __restrict__ gam,
                                   const float* __restrict__ bet) {
    int c = threadIdx.x;   // 256
    float mean = (float)(g_sum[c] / (double)NN);
    float var  = (float)(g_sumsq[c] / (double)NN) - mean * mean;
    float sc = gam[c] * rsqrtf(var + 1e-5f);
    g_scale[c] = sc;
    g_shift[c] = fmaf(-mean, sc, bet[c]);
}

__global__ void pool_kernel(const int* __restrict__ batch, int which) {
    int idx = blockIdx.x * 256 + threadIdx.x;   // 12500 x 256 (== N*32)
    int n = idx >> 5;
    int c = (idx & 31) << 2;
    int g = __ldg(&batch[n]);
    float4 v = *reinterpret_cast<const float4*>(&g_h[n * 128 + c]);
    float* p = &g_pool[(which * GG + g) * 128 + c];
    asm volatile("red.global.add.v4.f32 [%0], {%1,%2,%3,%4};"
                 :: "l"(p), "f"(v.x), "f"(v.y), "f"(v.z), "f"(v.w) : "memory");
    if ((idx & 31) == 0) atomicAdd(&g_cnt[which * GG + g], 1.0f);
}

__global__ void head1_kernel(const float* __restrict__ W, const float* __restrict__ b) {
    int g = blockIdx.x, j = threadIdx.x;   // 64 x 256
    __shared__ float xc[256];
    if (j < 128) xc[j] = g_pool[g * 128 + j] / fmaxf(g_cnt[g], 1.0f);
    else         xc[j] = g_pool[(GG + g) * 128 + (j - 128)] / fmaxf(g_cnt[GG + g], 1.0f);
    __syncthreads();
    float acc = b[j];
#pragma unroll 8
    for (int k = 0; k < 256; k++) acc = fmaf(xc[k], W[k * 256 + j], acc);
    g_fc1o[g * 256 + j] = fmaxf(acc, 0.f);
}

__global__ void head2_kernel(const float* __restrict__ W, const float* __restrict__ b) {
    int g = blockIdx.x, j = threadIdx.x;   // 64 x 64
    __shared__ float xin[256];
    for (int k = j; k < 256; k += 64) xin[k] = g_fc1o[g * 256 + k];
    __syncthreads();
    float acc = b[j];
#pragma unroll 8
    for (int k = 0; k < 256; k++) acc = fmaf(xin[k], W[k * 64 + j], acc);
    g_fc2o[g * 64 + j] = fmaxf(acc, 0.f);
}

__global__ void head3_kernel(const float* __restrict__ W, const float* __restrict__ b,
                             float* __restrict__ out) {
    int g = threadIdx.x;   // 1 x 64
    float acc = b[0];
#pragma unroll
    for (int k = 0; k < 64; k++) acc = fmaf(g_fc2o[g * 64 + k], W[k], acc);
    out[g] = 1.0f / (1.0f + expf(-acc));
}

// ---------------- orchestration -------------------------------------------
extern "C" void kernel_launch(void* const* d_in, const int* in_sizes, int n_in,
                              void* d_out, int out_size) {
    const float* x[2]     = { (const float*)d_in[0], (const float*)d_in[3] };
    const int*   ei[2]    = { (const int*)d_in[1],   (const int*)d_in[4] };
    const int*   batch[2] = { (const int*)d_in[2],   (const int*)d_in[5] };

    void* aggp = nullptr;
    cudaGetSymbolAddress(&aggp, g_agg);
    uint16_t *eB, *w1B, *w2B;
    cudaGetSymbolAddress((void**)&eB, g_eB);
    cudaGetSymbolAddress((void**)&w1B, g_w1B);
    cudaGetSymbolAddress((void**)&w2B, g_w2B);

    const int GRID_M = (NN + 127) / 128;   // 782

    zero_pool_kernel<<<64, 256>>>();

    for (int b = 0; b < 2; b++) {
        int o = 6 + b * 9;
        const float* embW = (const float*)d_in[o + 0];
        const float* embB = (const float*)d_in[o + 1];
        const float* W1   = (const float*)d_in[o + 2];
        const float* b1   = (const float*)d_in[o + 3];
        const float* gam  = (const float*)d_in[o + 4];
        const float* bet  = (const float*)d_in[o + 5];
        const float* W2   = (const float*)d_in[o + 6];
        const float* b2   = (const float*)d_in[o + 7];
        const float* eps  = (const float*)d_in[o + 8];

        // pre-convert this branch's weights to [n][k] bf16
        convB_kernel<<<dim3(256, 1), 256>>>(embW, eB, 1024, 128);
        convB_kernel<<<dim3(64, 4), 256>>>(W1, w1B, 128, 256);
        convB_kernel<<<dim3(64, 4), 256>>>(W2, w2B, 256, 128);

        mma_gemm<0><<<dim3(GRID_M, 1), 256>>>(x[b], eB, embB, nullptr);

        for (int i = 0; i < 4; i++) {
            cudaMemsetAsync(aggp, 0, (size_t)NN * 128 * sizeof(float), 0);
            scatter_kernel<<<200000, 256>>>(ei[b]);
            mma_gemm<1><<<dim3(GRID_M, 2), 256>>>(nullptr, w1B + (size_t)i * 256 * 128,
                                                  b1 + i * 256, eps + i);
            bn_finalize_kernel<<<1, 256>>>(gam + i * 256, bet + i * 256);
            mma_gemm<2><<<dim3(GRID_M, 1), 256>>>(nullptr, w2B + (size_t)i * 128 * 256,
                                                  b2 + i * 128, nullptr);
        }
        pool_kernel<<<12500, 256>>>(batch[b], b);
    }

    head1_kernel<<<64, 256>>>((const float*)d_in[24], (const float*)d_in[25]);
    head2_kernel<<<64, 64>>>((const float*)d_in[26], (const float*)d_in[27]);
    head3_kernel<<<1, 64>>>((const float*)d_in[28], (const float*)d_in[29], (float*)d_out);
}

// round 12
// speedup vs baseline: 1.0468x; 1.0468x over previous
#include <cuda_runtime.h>
#include <math.h>
#include <stdint.h>

#define NN 100000
#define EE 1600000
#define GG 64

// ---------------- scratch (device globals; no allocation allowed) ----------
__device__ float    g_h[NN * 128];
__device__ uint32_t g_hb[NN * 64];      // bf16x2 shadow of g_h (gather source)
__device__ float    g_agg[NN * 128];
__device__ float    g_z[NN * 256];
__device__ double   g_sum[256];
__device__ double   g_sumsq[256];
__device__ float    g_pool[2 * GG * 128];
__device__ float    g_cnt[2 * GG];
__device__ float    g_fc1o[GG * 256];
__device__ float    g_fc2o[GG * 64];
// preconverted weights, [n][k] bf16 (uint16), refreshed per branch
__device__ uint16_t g_eB[128 * 1024];          // embW: n=128, k=1024
__device__ uint16_t g_w1B[4 * 256 * 128];      // W1[i]: n=256, k=128
__device__ uint16_t g_w2B[4 * 128 * 256];      // W2[i]: n=128, k=256

// ---------------- helpers ---------------------------------------------------
__device__ __forceinline__ uint32_t cvt2(float e0, float e1) {
    uint32_t p;
    asm("cvt.rn.bf16x2.f32 %0, %1, %2;" : "=r"(p) : "f"(e1), "f"(e0));
    return p;
}

__device__ __forceinline__ void mma16816(float* c, const uint32_t* a, const uint32_t* b) {
    asm volatile("mma.sync.aligned.m16n8k16.row.col.f32.bf16.bf16.f32 "
                 "{%0,%1,%2,%3}, {%4,%5,%6,%7}, {%8,%9}, {%0,%1,%2,%3};"
                 : "+f"(c[0]), "+f"(c[1]), "+f"(c[2]), "+f"(c[3])
                 : "r"(a[0]), "r"(a[1]), "r"(a[2]), "r"(a[3]), "r"(b[0]), "r"(b[1]));
}

// ---------------- weight pre-conversion ------------------------------------
// src W is [K][Nn] fp32 (layer = blockIdx.y); dst H is [Nn][K] bf16
__global__ void convB_kernel(const float* __restrict__ W, uint16_t* __restrict__ H,
                             int K, int Nn) {
    const float* src = W + (size_t)blockIdx.y * K * Nn;
    uint32_t* dh = reinterpret_cast<uint32_t*>(H) + (size_t)blockIdx.y * (K * Nn / 2);
    int idx = blockIdx.x * 256 + threadIdx.x;          // over (K/2)*Nn
    if (idx >= (K / 2) * Nn) return;
    int k2 = idx / Nn, n = idx - k2 * Nn;
    float e0 = __ldg(&src[(size_t)(2 * k2) * Nn + n]);
    float e1 = __ldg(&src[(size_t)(2 * k2 + 1) * Nn + n]);
    dh[(size_t)n * (K / 2) + k2] = cvt2(e0, e1);
}

// ---------------- bf16 mma.sync GEMM (R10 loop, preconv B, fused BN) --------
// MODE 0: g_h[N,128] = Aext[N,1024] @ B + bias                      (+ g_hb)
// MODE 1: g_z[N,256] = g_agg[N,128] @ B + bias   (grid.y = 2; BN stats accum)
// MODE 2: g_h[N,128] = relu(relu(BN(g_z))[N,256] @ B + bias + g_h)  (+ g_hb)
//          (BN scale/shift computed per-CTA from g_sum/g_sumsq)
#define AS 40   // smem row stride in bf16 elems (80 B)

template <int MODE>
__global__ __launch_bounds__(256, 2)
void mma_gemm(const float* __restrict__ Aext, const uint16_t* __restrict__ BH,
              const float* __restrict__ bias,
              const float* __restrict__ gam, const float* __restrict__ bet)
{
    constexpr int K   = (MODE == 0) ? 1024 : ((MODE == 1) ? 128 : 256);
    constexpr int LDC = (MODE == 1) ? 256 : 128;
    constexpr int NCHUNK = K / 32;
    const float* A = (MODE == 0) ? Aext : ((MODE == 1) ? g_agg : g_z);
    float* C = (MODE == 1) ? g_z : g_h;

    __shared__ __align__(16) uint16_t Ahi[128 * AS];
    __shared__ __align__(16) uint16_t Bhi[128 * AS];
    __shared__ float s_sum[128], s_sumsq[128];
    __shared__ float s_scale[256], s_shift[256];

    const int tid  = threadIdx.x;
    const int lane = tid & 31, wid = tid >> 5;
    const int bm = blockIdx.x * 128;
    const int bn = blockIdx.y * 128;
    const int wm = (wid >> 1) * 32;
    const int wn = (wid & 1) * 64;
    const int grp = lane >> 2, qid = lane & 3;

    if (MODE == 1 && tid < 128) { s_sum[tid] = 0.f; s_sumsq[tid] = 0.f; }
    if (MODE == 2) {   // fused bn_finalize: every CTA computes scale/shift
        float mean = (float)(g_sum[tid] / (double)NN);
        float var  = (float)(g_sumsq[tid] / (double)NN) - mean * mean;
        float sc = __ldg(&gam[tid]) * rsqrtf(var + 1e-5f);
        s_scale[tid] = sc;
        s_shift[tid] = fmaf(-mean, sc, __ldg(&bet[tid]));
        __syncthreads();
    }

    float acc[2][8][4];
#pragma unroll
    for (int mt = 0; mt < 2; mt++)
#pragma unroll
        for (int nt = 0; nt < 8; nt++)
#pragma unroll
            for (int q = 0; q < 4; q++) acc[mt][nt][q] = 0.f;

    const int arow = tid >> 1, ahalf = tid & 1;        // A loader: row, 16-col half
    const int bnid = tid & 127, bkh = (tid >> 7) * 16; // B loader: n col, 16-k half
    const int rA = bm + arow;

    auto loadA = [&](int k0, float* v) {
        if (rA < NN) {
            const float* ap = A + (size_t)rA * K + k0 + ahalf * 16;
#pragma unroll
            for (int q = 0; q < 4; q++)
                *reinterpret_cast<float4*>(v + 4 * q) =
                    __ldg(reinterpret_cast<const float4*>(ap + 4 * q));
        } else {
#pragma unroll
            for (int j = 0; j < 16; j++) v[j] = 0.f;
        }
        if (MODE == 2) {
            const int kb = k0 + ahalf * 16;
#pragma unroll
            for (int j = 0; j < 16; j++)
                v[j] = fmaxf(fmaf(v[j], s_scale[kb + j], s_shift[kb + j]), 0.f);
        }
    };
    auto loadB = [&](int k0, uint32_t* vb) {   // 16 bf16 = 8 uint32, preconverted
        const uint32_t* ph = reinterpret_cast<const uint32_t*>(BH) +
                             ((size_t)(bn + bnid) * K + k0 + bkh) / 2;
        *reinterpret_cast<uint4*>(vb)     = __ldg(reinterpret_cast<const uint4*>(ph));
        *reinterpret_cast<uint4*>(vb + 4) = __ldg(reinterpret_cast<const uint4*>(ph + 4));
    };
    auto storeA = [&](const float* v) {
#pragma unroll
        for (int q = 0; q < 2; q++) {
            uint32_t hs[4];
#pragma unroll
            for (int p = 0; p < 4; p++)
                hs[p] = cvt2(v[q * 8 + p * 2], v[q * 8 + p * 2 + 1]);
            const int c = ahalf * 16 + q * 8;
            *reinterpret_cast<uint4*>(&Ahi[arow * AS + c]) = make_uint4(hs[0], hs[1], hs[2], hs[3]);
        }
    };
    auto storeB = [&](const uint32_t* vb) {
        *reinterpret_cast<uint4*>(&Bhi[bnid * AS + bkh])     = *reinterpret_cast<const uint4*>(vb);
        *reinterpret_cast<uint4*>(&Bhi[bnid * AS + bkh + 8]) = *reinterpret_cast<const uint4*>(vb + 4);
    };
    auto mmaStep = [&]() {
#pragma unroll
        for (int s = 0; s < 32; s += 16) {
            uint32_t ah[2][4];
#pragma unroll
            for (int mt = 0; mt < 2; mt++) {
                const int r0 = (wm + mt * 16 + grp) * AS + s + qid * 2;
                const int r8 = r0 + 8 * AS;
                ah[mt][0] = *reinterpret_cast<const uint32_t*>(&Ahi[r0]);
                ah[mt][1] = *reinterpret_cast<const uint32_t*>(&Ahi[r8]);
                ah[mt][2] = *reinterpret_cast<const uint32_t*>(&Ahi[r0 + 8]);
                ah[mt][3] = *reinterpret_cast<const uint32_t*>(&Ahi[r8 + 8]);
            }
#pragma unroll
            for (int nt = 0; nt < 8; nt++) {
                const int nb = (wn + nt * 8 + grp) * AS + s + qid * 2;
                uint32_t bh[2];
                bh[0] = *reinterpret_cast<const uint32_t*>(&Bhi[nb]);
                bh[1] = *reinterpret_cast<const uint32_t*>(&Bhi[nb + 8]);
#pragma unroll
                for (int mt = 0; mt < 2; mt++)
                    mma16816(acc[mt][nt], ah[mt], bh);
            }
        }
    };

    // ---- prologue: chunk 0 ----
    {
        float va[16]; uint32_t vb[8];
        loadA(0, va); loadB(0, vb);
        storeA(va);   storeB(vb);
    }
    __syncthreads();

    // ---- pipelined main loop (R10 structure: two syncs, single buffer) ----
    for (int ch = 0; ch < NCHUNK - 1; ch++) {
        float wa[16]; uint32_t wb[8];
        loadA((ch + 1) * 32, wa);
        loadB((ch + 1) * 32, wb);
        mmaStep();
        __syncthreads();
        storeA(wa); storeB(wb);
        __syncthreads();
    }
    mmaStep();

    // ---- epilogue (fused bias / residual / ReLU / bf16 shadow / BN stats) ----
#pragma unroll
    for (int nt = 0; nt < 8; nt++) {
        const int ccl = wn + nt * 8 + qid * 2;
        const int cc  = bn + ccl;
        const float b0 = bias[cc], b1 = bias[cc + 1];
        float cs0 = 0.f, cs1 = 0.f, cq0 = 0.f, cq1 = 0.f;
#pragma unroll
        for (int mt = 0; mt < 2; mt++) {
            const int r0 = bm + wm + mt * 16 + grp;
#pragma unroll
            for (int hrow = 0; hrow < 2; hrow++) {
                const int r = r0 + hrow * 8;
                if (r < NN) {
                    float2 o;
                    o.x = acc[mt][nt][hrow * 2 + 0] + b0;
                    o.y = acc[mt][nt][hrow * 2 + 1] + b1;
                    if (MODE == 2) {
                        const float2 h = *reinterpret_cast<const float2*>(&g_h[(size_t)r * 128 + cc]);
                        o.x = fmaxf(o.x + h.x, 0.f);
                        o.y = fmaxf(o.y + h.y, 0.f);
                    }
                    *reinterpret_cast<float2*>(&C[(size_t)r * LDC + cc]) = o;
                    if (MODE == 0 || MODE == 2)
                        g_hb[((size_t)r * 128 + cc) >> 1] = cvt2(o.x, o.y);
                    if (MODE == 1) {
                        cs0 += o.x; cq0 = fmaf(o.x, o.x, cq0);
                        cs1 += o.y; cq1 = fmaf(o.y, o.y, cq1);
                    }
                }
            }
        }
        if (MODE == 1) {
            atomicAdd(&s_sum[ccl],       cs0);
            atomicAdd(&s_sum[ccl + 1],   cs1);
            atomicAdd(&s_sumsq[ccl],     cq0);
            atomicAdd(&s_sumsq[ccl + 1], cq1);
        }
    }
    if (MODE == 1) {
        __syncthreads();
        if (tid < 128) {
            atomicAdd(&g_sum[bn + tid],   (double)s_sum[tid]);
            atomicAdd(&g_sumsq[bn + tid], (double)s_sumsq[tid]);
        }
    }
}

// ---------------- small utility kernels -----------------------------------
__global__ void zero_pool_kernel() {
    int i = blockIdx.x * 256 + threadIdx.x;
    g_pool[i] = 0.f;
    if (i < 2 * GG) g_cnt[i] = 0.f;
}

// g_agg = (1+eps) * h (read from bf16 shadow); block 0 zeroes BN accumulators.
__global__ void init_agg_kernel(const float* __restrict__ eps) {
    int i = blockIdx.x * 256 + threadIdx.x;   // 12500 x 256, 4 floats each
    if (blockIdx.x == 0) { g_sum[threadIdx.x] = 0.0; g_sumsq[threadIdx.x] = 0.0; }
    float e = 1.0f + __ldg(eps);
    uint2 v = *reinterpret_cast<const uint2*>(&g_hb[i * 2]);
    float4 o;
    o.x = e * __uint_as_float(v.x << 16);
    o.y = e * __uint_as_float(v.x & 0xFFFF0000u);
    o.z = e * __uint_as_float(v.y << 16);
    o.w = e * __uint_as_float(v.y & 0xFFFF0000u);
    *reinterpret_cast<float4*>(&g_agg[i * 4]) = o;
}

// warp per edge: gather bf16 row (256B), vector-reduce fp32 into agg[dst]
__global__ void scatter_kernel(const int* __restrict__ ei) {
    int idx = blockIdx.x * 256 + threadIdx.x;  // 200000 x 256 (== E*32)
    int e = idx >> 5;
    int c = idx & 31;
    int src = __ldg(&ei[e]);
    int dst = __ldg(&ei[EE + e]);
    uint2 v = *reinterpret_cast<const uint2*>(&g_hb[src * 64 + c * 2]);
    float f0 = __uint_as_float(v.x << 16);
    float f1 = __uint_as_float(v.x & 0xFFFF0000u);
    float f2 = __uint_as_float(v.y << 16);
    float f3 = __uint_as_float(v.y & 0xFFFF0000u);
    float* p = &g_agg[dst * 128 + c * 4];
    asm volatile("red.global.add.v4.f32 [%0], {%1,%2,%3,%4};"
                 :: "l"(p), "f"(f0), "f"(f1), "f"(f2), "f"(f3) : "memory");
}

__global__ void pool_kernel(const int* __restrict__ batch, int which) {
    int idx = blockIdx.x * 256 + threadIdx.x;   // 12500 x 256 (== N*32)
    int n = idx >> 5;
    int c = (idx & 31) << 2;
    int g = __ldg(&batch[n]);
    float4 v = *reinterpret_cast<const float4*>(&g_h[n * 128 + c]);
    float* p = &g_pool[(which * GG + g) * 128 + c];
    asm volatile("red.global.add.v4.f32 [%0], {%1,%2,%3,%4};"
                 :: "l"(p), "f"(v.x), "f"(v.y), "f"(v.z), "f"(v.w) : "memory");
    if ((idx & 31) == 0) atomicAdd(&g_cnt[which * GG + g], 1.0f);
}

__global__ void head1_kernel(const float* __restrict__ W, const float* __restrict__ b) {
    int g = blockIdx.x, j = threadIdx.x;   // 64 x 256
    __shared__ float xc[256];
    if (j < 128) xc[j] = g_pool[g * 128 + j] / fmaxf(g_cnt[g], 1.0f);
    else         xc[j] = g_pool[(GG + g) * 128 + (j - 128)] / fmaxf(g_cnt[GG + g], 1.0f);
    __syncthreads();
    float acc = b[j];
#pragma unroll 8
    for (int k = 0; k < 256; k++) acc = fmaf(xc[k], W[k * 256 + j], acc);
    g_fc1o[g * 256 + j] = fmaxf(acc, 0.f);
}

__global__ void head2_kernel(const float* __restrict__ W, const float* __restrict__ b) {
    int g = blockIdx.x, j = threadIdx.x;   // 64 x 64
    __shared__ float xin[256];
    for (int k = j; k < 256; k += 64) xin[k] = g_fc1o[g * 256 + k];
    __syncthreads();
    float acc = b[j];
#pragma unroll 8
    for (int k = 0; k < 256; k++) acc = fmaf(xin[k], W[k * 64 + j], acc);
    g_fc2o[g * 64 + j] = fmaxf(acc, 0.f);
}

__global__ void head3_kernel(const float* __restrict__ W, const float* __restrict__ b,
                             float* __restrict__ out) {
    int g = threadIdx.x;   // 1 x 64
    float acc = b[0];
#pragma unroll
    for (int k = 0; k < 64; k++) acc = fmaf(g_fc2o[g * 64 + k], W[k], acc);
    out[g] = 1.0f / (1.0f + expf(-acc));
}

// ---------------- orchestration -------------------------------------------
extern "C" void kernel_launch(void* const* d_in, const int* in_sizes, int n_in,
                              void* d_out, int out_size) {
    const float* x[2]     = { (const float*)d_in[0], (const float*)d_in[3] };
    const int*   ei[2]    = { (const int*)d_in[1],   (const int*)d_in[4] };
    const int*   batch[2] = { (const int*)d_in[2],   (const int*)d_in[5] };

    uint16_t *eB, *w1B, *w2B;
    cudaGetSymbolAddress((void**)&eB, g_eB);
    cudaGetSymbolAddress((void**)&w1B, g_w1B);
    cudaGetSymbolAddress((void**)&w2B, g_w2B);

    const int GRID_M = (NN + 127) / 128;   // 782

    zero_pool_kernel<<<64, 256>>>();

    for (int b = 0; b < 2; b++) {
        int o = 6 + b * 9;
        const float* embW = (const float*)d_in[o + 0];
        const float* embB = (const float*)d_in[o + 1];
        const float* W1   = (const float*)d_in[o + 2];
        const float* b1   = (const float*)d_in[o + 3];
        const float* gam  = (const float*)d_in[o + 4];
        const float* bet  = (const float*)d_in[o + 5];
        const float* W2   = (const float*)d_in[o + 6];
        const float* b2   = (const float*)d_in[o + 7];
        const float* eps  = (const float*)d_in[o + 8];

        // pre-convert this branch's weights to [n][k] bf16
        convB_kernel<<<dim3(256, 1), 256>>>(embW, eB, 1024, 128);
        convB_kernel<<<dim3(64, 4), 256>>>(W1, w1B, 128, 256);
        convB_kernel<<<dim3(64, 4), 256>>>(W2, w2B, 256, 128);

        mma_gemm<0><<<dim3(GRID_M, 1), 256>>>(x[b], eB, embB, nullptr, nullptr);

        for (int i = 0; i < 4; i++) {
            init_agg_kernel<<<12500, 256>>>(eps + i);
            scatter_kernel<<<200000, 256>>>(ei[b]);
            mma_gemm<1><<<dim3(GRID_M, 2), 256>>>(nullptr, w1B + (size_t)i * 256 * 128,
                                                  b1 + i * 256, nullptr, nullptr);
            mma_gemm<2><<<dim3(GRID_M, 1), 256>>>(nullptr, w2B + (size_t)i * 128 * 256,
                                                  b2 + i * 128, gam + i * 256, bet + i * 256);
        }
        pool_kernel<<<12500, 256>>>(batch[b], b);
    }

    head1_kernel<<<64, 256>>>((const float*)d_in[24], (const float*)d_in[25]);
    head2_kernel<<<64, 64>>>((const float*)d_in[26], (const float*)d_in[27]);
    head3_kernel<<<1, 64>>>((const float*)d_in[28], (const float*)d_in[29], (float*)d_out);
}

// round 13
// speedup vs baseline: 1.0908x; 1.0421x over previous
#include <cuda_runtime.h>
#include <math.h>
#include <stdint.h>

#define NN 100000
#define EE 1600000
#define GG 64

// ---------------- scratch (device globals; no allocation allowed) ----------
__device__ uint32_t g_hb[NN * 64];      // bf16x2 h (the ONLY h tensor)
__device__ uint32_t g_zb[NN * 128];     // bf16x2 z (MLP hidden, pre-BN)
__device__ float    g_agg[NN * 128];
__device__ double   g_sum[256];
__device__ double   g_sumsq[256];
__device__ float    g_pool[2 * GG * 128];
__device__ float    g_cnt[2 * GG];
__device__ float    g_fc1o[GG * 256];
__device__ float    g_fc2o[GG * 64];
// preconverted weights, [n][k] bf16 (uint16), refreshed per branch
__device__ uint16_t g_eB[128 * 1024];          // embW: n=128, k=1024
__device__ uint16_t g_w1B[4 * 256 * 128];      // W1[i]: n=256, k=128
__device__ uint16_t g_w2B[4 * 128 * 256];      // W2[i]: n=128, k=256

// ---------------- helpers ---------------------------------------------------
__device__ __forceinline__ uint32_t cvt2(float e0, float e1) {
    uint32_t p;
    asm("cvt.rn.bf16x2.f32 %0, %1, %2;" : "=r"(p) : "f"(e1), "f"(e0));
    return p;
}
__device__ __forceinline__ float bflo(uint32_t u) { return __uint_as_float(u << 16); }
__device__ __forceinline__ float bfhi(uint32_t u) { return __uint_as_float(u & 0xFFFF0000u); }

__device__ __forceinline__ void mma16816(float* c, const uint32_t* a, const uint32_t* b) {
    asm volatile("mma.sync.aligned.m16n8k16.row.col.f32.bf16.bf16.f32 "
                 "{%0,%1,%2,%3}, {%4,%5,%6,%7}, {%8,%9}, {%0,%1,%2,%3};"
                 : "+f"(c[0]), "+f"(c[1]), "+f"(c[2]), "+f"(c[3])
                 : "r"(a[0]), "r"(a[1]), "r"(a[2]), "r"(a[3]), "r"(b[0]), "r"(b[1]));
}

// ---------------- weight pre-conversion ------------------------------------
// src W is [K][Nn] fp32 (layer = blockIdx.y); dst H is [Nn][K] bf16
__global__ void convB_kernel(const float* __restrict__ W, uint16_t* __restrict__ H,
                             int K, int Nn) {
    const float* src = W + (size_t)blockIdx.y * K * Nn;
    uint32_t* dh = reinterpret_cast<uint32_t*>(H) + (size_t)blockIdx.y * (K * Nn / 2);
    int idx = blockIdx.x * 256 + threadIdx.x;          // over (K/2)*Nn
    if (idx >= (K / 2) * Nn) return;
    int k2 = idx / Nn, n = idx - k2 * Nn;
    float e0 = __ldg(&src[(size_t)(2 * k2) * Nn + n]);
    float e1 = __ldg(&src[(size_t)(2 * k2 + 1) * Nn + n]);
    dh[(size_t)n * (K / 2) + k2] = cvt2(e0, e1);
}

// ---------------- bf16 mma.sync GEMM (R12 loop, bf16 intermediates) ---------
// MODE 0: hb[N,128] = bf16( Aext[N,1024] @ B + bias )
// MODE 1: zb[N,256] = bf16( g_agg[N,128] @ B + bias )  (grid.y=2; BN stats fp32)
// MODE 2: hb[N,128] = bf16( relu(relu(BN(zb))[N,256] @ B + bias + hb) )
//          (BN scale/shift computed per-CTA from g_sum/g_sumsq)
#define AS 40   // smem row stride in bf16 elems (80 B)

template <int MODE>
__global__ __launch_bounds__(256, 2)
void mma_gemm(const float* __restrict__ Aext, const uint16_t* __restrict__ BH,
              const float* __restrict__ bias,
              const float* __restrict__ gam, const float* __restrict__ bet)
{
    constexpr int K   = (MODE == 0) ? 1024 : ((MODE == 1) ? 128 : 256);
    constexpr int NCHUNK = K / 32;

    __shared__ __align__(16) uint16_t Ahi[128 * AS];
    __shared__ __align__(16) uint16_t Bhi[128 * AS];
    __shared__ float s_sum[128], s_sumsq[128];
    __shared__ float s_scale[256], s_shift[256];

    const int tid  = threadIdx.x;
    const int lane = tid & 31, wid = tid >> 5;
    const int bm = blockIdx.x * 128;
    const int bn = blockIdx.y * 128;
    const int wm = (wid >> 1) * 32;
    const int wn = (wid & 1) * 64;
    const int grp = lane >> 2, qid = lane & 3;

    if (MODE == 1 && tid < 128) { s_sum[tid] = 0.f; s_sumsq[tid] = 0.f; }
    if (MODE == 2) {   // fused bn_finalize: every CTA computes scale/shift
        float mean = (float)(g_sum[tid] / (double)NN);
        float var  = (float)(g_sumsq[tid] / (double)NN) - mean * mean;
        float sc = __ldg(&gam[tid]) * rsqrtf(var + 1e-5f);
        s_scale[tid] = sc;
        s_shift[tid] = fmaf(-mean, sc, __ldg(&bet[tid]));
        __syncthreads();
    }

    float acc[2][8][4];
#pragma unroll
    for (int mt = 0; mt < 2; mt++)
#pragma unroll
        for (int nt = 0; nt < 8; nt++)
#pragma unroll
            for (int q = 0; q < 4; q++) acc[mt][nt][q] = 0.f;

    const int arow = tid >> 1, ahalf = tid & 1;        // A loader: row, 16-col half
    const int bnid = tid & 127, bkh = (tid >> 7) * 16; // B loader: n col, 16-k half
    const int rA = bm + arow;

    auto loadA = [&](int k0, float* v) {
        if (rA < NN) {
            if (MODE == 2) {             // bf16 z read: 16 bf16 = 8 uint32
                const uint32_t* zp = g_zb + ((size_t)rA * 256 + k0 + ahalf * 16) / 2;
                uint32_t u[8];
                *reinterpret_cast<uint4*>(u)     = __ldg(reinterpret_cast<const uint4*>(zp));
                *reinterpret_cast<uint4*>(u + 4) = __ldg(reinterpret_cast<const uint4*>(zp + 4));
                const int kb = k0 + ahalf * 16;
#pragma unroll
                for (int j = 0; j < 8; j++) {
                    v[2 * j + 0] = fmaxf(fmaf(bflo(u[j]), s_scale[kb + 2 * j],     s_shift[kb + 2 * j]), 0.f);
                    v[2 * j + 1] = fmaxf(fmaf(bfhi(u[j]), s_scale[kb + 2 * j + 1], s_shift[kb + 2 * j + 1]), 0.f);
                }
            } else {                     // fp32 A read (MODE0: x, MODE1: agg)
                const float* ap = ((MODE == 0) ? Aext : g_agg) +
                                  (size_t)rA * K + k0 + ahalf * 16;
#pragma unroll
                for (int q = 0; q < 4; q++)
                    *reinterpret_cast<float4*>(v + 4 * q) =
                        __ldg(reinterpret_cast<const float4*>(ap + 4 * q));
            }
        } else {
#pragma unroll
            for (int j = 0; j < 16; j++) v[j] = 0.f;
        }
    };
    auto loadB = [&](int k0, uint32_t* vb) {   // 16 bf16 = 8 uint32, preconverted
        const uint32_t* ph = reinterpret_cast<const uint32_t*>(BH) +
                             ((size_t)(bn + bnid) * K + k0 + bkh) / 2;
        *reinterpret_cast<uint4*>(vb)     = __ldg(reinterpret_cast<const uint4*>(ph));
        *reinterpret_cast<uint4*>(vb + 4) = __ldg(reinterpret_cast<const uint4*>(ph + 4));
    };
    auto storeA = [&](const float* v) {
#pragma unroll
        for (int q = 0; q < 2; q++) {
            uint32_t hs[4];
#pragma unroll
            for (int p = 0; p < 4; p++)
                hs[p] = cvt2(v[q * 8 + p * 2], v[q * 8 + p * 2 + 1]);
            const int c = ahalf * 16 + q * 8;
            *reinterpret_cast<uint4*>(&Ahi[arow * AS + c]) = make_uint4(hs[0], hs[1], hs[2], hs[3]);
        }
    };
    auto storeB = [&](const uint32_t* vb) {
        *reinterpret_cast<uint4*>(&Bhi[bnid * AS + bkh])     = *reinterpret_cast<const uint4*>(vb);
        *reinterpret_cast<uint4*>(&Bhi[bnid * AS + bkh + 8]) = *reinterpret_cast<const uint4*>(vb + 4);
    };
    auto mmaStep = [&]() {
#pragma unroll
        for (int s = 0; s < 32; s += 16) {
            uint32_t ah[2][4];
#pragma unroll
            for (int mt = 0; mt < 2; mt++) {
                const int r0 = (wm + mt * 16 + grp) * AS + s + qid * 2;
                const int r8 = r0 + 8 * AS;
                ah[mt][0] = *reinterpret_cast<const uint32_t*>(&Ahi[r0]);
                ah[mt][1] = *reinterpret_cast<const uint32_t*>(&Ahi[r8]);
                ah[mt][2] = *reinterpret_cast<const uint32_t*>(&Ahi[r0 + 8]);
                ah[mt][3] = *reinterpret_cast<const uint32_t*>(&Ahi[r8 + 8]);
            }
#pragma unroll
            for (int nt = 0; nt < 8; nt++) {
                const int nb = (wn + nt * 8 + grp) * AS + s + qid * 2;
                uint32_t bh[2];
                bh[0] = *reinterpret_cast<const uint32_t*>(&Bhi[nb]);
                bh[1] = *reinterpret_cast<const uint32_t*>(&Bhi[nb + 8]);
#pragma unroll
                for (int mt = 0; mt < 2; mt++)
                    mma16816(acc[mt][nt], ah[mt], bh);
            }
        }
    };

    // ---- prologue: chunk 0 ----
    {
        float va[16]; uint32_t vb[8];
        loadA(0, va); loadB(0, vb);
        storeA(va);   storeB(vb);
    }
    __syncthreads();

    // ---- pipelined main loop (R10/R12 structure: two syncs, single buffer) ----
    for (int ch = 0; ch < NCHUNK - 1; ch++) {
        float wa[16]; uint32_t wb[8];
        loadA((ch + 1) * 32, wa);
        loadB((ch + 1) * 32, wb);
        mmaStep();
        __syncthreads();
        storeA(wa); storeB(wb);
        __syncthreads();
    }
    mmaStep();

    // ---- epilogue: bias / residual / ReLU -> bf16 outputs (+ BN stats) ----
#pragma unroll
    for (int nt = 0; nt < 8; nt++) {
        const int ccl = wn + nt * 8 + qid * 2;
        const int cc  = bn + ccl;
        const float b0 = bias[cc], b1 = bias[cc + 1];
        float cs0 = 0.f, cs1 = 0.f, cq0 = 0.f, cq1 = 0.f;
#pragma unroll
        for (int mt = 0; mt < 2; mt++) {
            const int r0 = bm + wm + mt * 16 + grp;
#pragma unroll
            for (int hrow = 0; hrow < 2; hrow++) {
                const int r = r0 + hrow * 8;
                if (r < NN) {
                    float2 o;
                    o.x = acc[mt][nt][hrow * 2 + 0] + b0;
                    o.y = acc[mt][nt][hrow * 2 + 1] + b1;
                    if (MODE == 2) {     // residual from bf16 h
                        uint32_t hu = g_hb[((size_t)r * 128 + cc) >> 1];
                        o.x = fmaxf(o.x + bflo(hu), 0.f);
                        o.y = fmaxf(o.y + bfhi(hu), 0.f);
                    }
                    if (MODE == 1) {
                        cs0 += o.x; cq0 = fmaf(o.x, o.x, cq0);
                        cs1 += o.y; cq1 = fmaf(o.y, o.y, cq1);
                        g_zb[((size_t)r * 256 + cc) >> 1] = cvt2(o.x, o.y);
                    } else {
                        g_hb[((size_t)r * 128 + cc) >> 1] = cvt2(o.x, o.y);
                    }
                }
            }
        }
        if (MODE == 1) {
            atomicAdd(&s_sum[ccl],       cs0);
            atomicAdd(&s_sum[ccl + 1],   cs1);
            atomicAdd(&s_sumsq[ccl],     cq0);
            atomicAdd(&s_sumsq[ccl + 1], cq1);
        }
    }
    if (MODE == 1) {
        __syncthreads();
        if (tid < 128) {
            atomicAdd(&g_sum[bn + tid],   (double)s_sum[tid]);
            atomicAdd(&g_sumsq[bn + tid], (double)s_sumsq[tid]);
        }
    }
}

// ---------------- small utility kernels -----------------------------------
__global__ void zero_pool_kernel() {
    int i = blockIdx.x * 256 + threadIdx.x;
    g_pool[i] = 0.f;
    if (i < 2 * GG) g_cnt[i] = 0.f;
}

// g_agg = (1+eps) * h (from bf16 shadow); block 0 zeroes BN accumulators.
__global__ void init_agg_kernel(const float* __restrict__ eps) {
    int i = blockIdx.x * 256 + threadIdx.x;   // 12500 x 256, 4 floats each
    if (blockIdx.x == 0) { g_sum[threadIdx.x] = 0.0; g_sumsq[threadIdx.x] = 0.0; }
    float e = 1.0f + __ldg(eps);
    uint2 v = *reinterpret_cast<const uint2*>(&g_hb[i * 2]);
    float4 o;
    o.x = e * bflo(v.x);
    o.y = e * bfhi(v.x);
    o.z = e * bflo(v.y);
    o.w = e * bfhi(v.y);
    *reinterpret_cast<float4*>(&g_agg[i * 4]) = o;
}

// warp per edge: gather bf16 row (256B), vector-reduce fp32 into agg[dst]
__global__ void scatter_kernel(const int* __restrict__ ei) {
    int idx = blockIdx.x * 256 + threadIdx.x;  // 200000 x 256 (== E*32)
    int e = idx >> 5;
    int c = idx & 31;
    int src = __ldg(&ei[e]);
    int dst = __ldg(&ei[EE + e]);
    uint2 v = *reinterpret_cast<const uint2*>(&g_hb[src * 64 + c * 2]);
    float f0 = bflo(v.x), f1 = bfhi(v.x), f2 = bflo(v.y), f3 = bfhi(v.y);
    float* p = &g_agg[dst * 128 + c * 4];
    asm volatile("red.global.add.v4.f32 [%0], {%1,%2,%3,%4};"
                 :: "l"(p), "f"(f0), "f"(f1), "f"(f2), "f"(f3) : "memory");
}

__global__ void pool_kernel(const int* __restrict__ batch, int which) {
    int idx = blockIdx.x * 256 + threadIdx.x;   // 12500 x 256 (== N*32)
    int n = idx >> 5;
    int c = idx & 31;
    int g = __ldg(&batch[n]);
    uint2 v = *reinterpret_cast<const uint2*>(&g_hb[n * 64 + c * 2]);
    float f0 = bflo(v.x), f1 = bfhi(v.x), f2 = bflo(v.y), f3 = bfhi(v.y);
    float* p = &g_pool[(which * GG + g) * 128 + c * 4];
    asm volatile("red.global.add.v4.f32 [%0], {%1,%2,%3,%4};"
                 :: "l"(p), "f"(f0), "f"(f1), "f"(f2), "f"(f3) : "memory");
    if ((idx & 31) == 0) atomicAdd(&g_cnt[which * GG + g], 1.0f);
}

__global__ void head1_kernel(const float* __restrict__ W, const float* __restrict__ b) {
    int g = blockIdx.x, j = threadIdx.x;   // 64 x 256
    __shared__ float xc[256];
    if (j < 128) xc[j] = g_pool[g * 128 + j] / fmaxf(g_cnt[g], 1.0f);
    else         xc[j] = g_pool[(GG + g) * 128 + (j - 128)] / fmaxf(g_cnt[GG + g], 1.0f);
    __syncthreads();
    float acc = b[j];
#pragma unroll 8
    for (int k = 0; k < 256; k++) acc = fmaf(xc[k], W[k * 256 + j], acc);
    g_fc1o[g * 256 + j] = fmaxf(acc, 0.f);
}

__global__ void head2_kernel(const float* __restrict__ W, const float* __restrict__ b) {
    int g = blockIdx.x, j = threadIdx.x;   // 64 x 64
    __shared__ float xin[256];
    for (int k = j; k < 256; k += 64) xin[k] = g_fc1o[g * 256 + k];
    __syncthreads();
    float acc = b[j];
#pragma unroll 8
    for (int k = 0; k < 256; k++) acc = fmaf(xin[k], W[k * 64 + j], acc);
    g_fc2o[g * 64 + j] = fmaxf(acc, 0.f);
}

__global__ void head3_kernel(const float* __restrict__ W, const float* __restrict__ b,
                             float* __restrict__ out) {
    int g = threadIdx.x;   // 1 x 64
    float acc = b[0];
#pragma unroll
    for (int k = 0; k < 64; k++) acc = fmaf(g_fc2o[g * 64 + k], W[k], acc);
    out[g] = 1.0f / (1.0f + expf(-acc));
}

// ---------------- orchestration -------------------------------------------
extern "C" void kernel_launch(void* const* d_in, const int* in_sizes, int n_in,
                              void* d_out, int out_size) {
    const float* x[2]     = { (const float*)d_in[0], (const float*)d_in[3] };
    const int*   ei[2]    = { (const int*)d_in[1],   (const int*)d_in[4] };
    const int*   batch[2] = { (const int*)d_in[2],   (const int*)d_in[5] };

    uint16_t *eB, *w1B, *w2B;
    cudaGetSymbolAddress((void**)&eB, g_eB);
    cudaGetSymbolAddress((void**)&w1B, g_w1B);
    cudaGetSymbolAddress((void**)&w2B, g_w2B);

    const int GRID_M = (NN + 127) / 128;   // 782

    zero_pool_kernel<<<64, 256>>>();

    for (int b = 0; b < 2; b++) {
        int o = 6 + b * 9;
        const float* embW = (const float*)d_in[o + 0];
        const float* embB = (const float*)d_in[o + 1];
        const float* W1   = (const float*)d_in[o + 2];
        const float* b1   = (const float*)d_in[o + 3];
        const float* gam  = (const float*)d_in[o + 4];
        const float* bet  = (const float*)d_in[o + 5];
        const float* W2   = (const float*)d_in[o + 6];
        const float* b2   = (const float*)d_in[o + 7];
        const float* eps  = (const float*)d_in[o + 8];

        // pre-convert this branch's weights to [n][k] bf16
        convB_kernel<<<dim3(256, 1), 256>>>(embW, eB, 1024, 128);
        convB_kernel<<<dim3(64, 4), 256>>>(W1, w1B, 128, 256);
        convB_kernel<<<dim3(64, 4), 256>>>(W2, w2B, 256, 128);

        mma_gemm<0><<<dim3(GRID_M, 1), 256>>>(x[b], eB, embB, nullptr, nullptr);

        for (int i = 0; i < 4; i++) {
            init_agg_kernel<<<12500, 256>>>(eps + i);
            scatter_kernel<<<200000, 256>>>(ei[b]);
            mma_gemm<1><<<dim3(GRID_M, 2), 256>>>(nullptr, w1B + (size_t)i * 256 * 128,
                                                  b1 + i * 256, nullptr, nullptr);
            mma_gemm<2><<<dim3(GRID_M, 1), 256>>>(nullptr, w2B + (size_t)i * 128 * 256,
                                                  b2 + i * 128, gam + i * 256, bet + i * 256);
        }
        pool_kernel<<<12500, 256>>>(batch[b], b);
    }

    head1_kernel<<<64, 256>>>((const float*)d_in[24], (const float*)d_in[25]);
    head2_kernel<<<64, 64>>>((const float*)d_in[26], (const float*)d_in[27]);
    head3_kernel<<<1, 64>>>((const float*)d_in[28], (const float*)d_in[29], (float*)d_out);
}

// round 14
// speedup vs baseline: 1.4005x; 1.2839x over previous
#include <cuda_runtime.h>
#include <math.h>
#include <stdint.h>

#define NN 100000
#define EE 1600000
#define GG 64

// ---------------- scratch (device globals; no allocation allowed) ----------
__device__ uint32_t g_hb[NN * 64];      // bf16x2 h (the ONLY h tensor)
__device__ uint32_t g_zb[NN * 128];     // bf16x2 z (MLP hidden, pre-BN)
__device__ uint32_t g_aggb[NN * 64];    // bf16x2 agg = (1+eps)h + sum h[src]
__device__ double   g_sum[256];
__device__ double   g_sumsq[256];
__device__ float    g_pool[2 * GG * 128];
__device__ float    g_cnt[2 * GG];
__device__ float    g_fc1o[GG * 256];
__device__ float    g_fc2o[GG * 64];
// preconverted weights, [n][k] bf16 (uint16), refreshed per branch
__device__ uint16_t g_eB[128 * 1024];          // embW: n=128, k=1024
__device__ uint16_t g_w1B[4 * 256 * 128];      // W1[i]: n=256, k=128
__device__ uint16_t g_w2B[4 * 128 * 256];      // W2[i]: n=128, k=256

// ---------------- helpers ---------------------------------------------------
__device__ __forceinline__ uint32_t cvt2(float e0, float e1) {
    uint32_t p;
    asm("cvt.rn.bf16x2.f32 %0, %1, %2;" : "=r"(p) : "f"(e1), "f"(e0));
    return p;
}
__device__ __forceinline__ float bflo(uint32_t u) { return __uint_as_float(u << 16); }
__device__ __forceinline__ float bfhi(uint32_t u) { return __uint_as_float(u & 0xFFFF0000u); }

__device__ __forceinline__ void mma16816(float* c, const uint32_t* a, const uint32_t* b) {
    asm volatile("mma.sync.aligned.m16n8k16.row.col.f32.bf16.bf16.f32 "
                 "{%0,%1,%2,%3}, {%4,%5,%6,%7}, {%8,%9}, {%0,%1,%2,%3};"
                 : "+f"(c[0]), "+f"(c[1]), "+f"(c[2]), "+f"(c[3])
                 : "r"(a[0]), "r"(a[1]), "r"(a[2]), "r"(a[3]), "r"(b[0]), "r"(b[1]));
}

// ---------------- weight pre-conversion ------------------------------------
// src W is [K][Nn] fp32 (layer = blockIdx.y); dst H is [Nn][K] bf16
__global__ void convB_kernel(const float* __restrict__ W, uint16_t* __restrict__ H,
                             int K, int Nn) {
    const float* src = W + (size_t)blockIdx.y * K * Nn;
    uint32_t* dh = reinterpret_cast<uint32_t*>(H) + (size_t)blockIdx.y * (K * Nn / 2);
    int idx = blockIdx.x * 256 + threadIdx.x;          // over (K/2)*Nn
    if (idx >= (K / 2) * Nn) return;
    int k2 = idx / Nn, n = idx - k2 * Nn;
    float e0 = __ldg(&src[(size_t)(2 * k2) * Nn + n]);
    float e1 = __ldg(&src[(size_t)(2 * k2 + 1) * Nn + n]);
    dh[(size_t)n * (K / 2) + k2] = cvt2(e0, e1);
}

// ---------------- bf16 mma.sync GEMM (R12 loop, all-bf16 intermediates) ------
// MODE 0: hb[N,128] = bf16( Aext[N,1024] @ B + bias )
// MODE 1: zb[N,256] = bf16( aggb[N,128] @ B + bias )  (grid.y=2; BN stats fp32)
// MODE 2: hb[N,128] = bf16( relu(relu(BN(zb))[N,256] @ B + bias + hb) )
//          (BN scale/shift computed per-CTA from g_sum/g_sumsq)
#define AS 40   // smem row stride in bf16 elems (80 B)

template <int MODE>
__global__ __launch_bounds__(256, 2)
void mma_gemm(const float* __restrict__ Aext, const uint16_t* __restrict__ BH,
              const float* __restrict__ bias,
              const float* __restrict__ gam, const float* __restrict__ bet)
{
    constexpr int K   = (MODE == 0) ? 1024 : ((MODE == 1) ? 128 : 256);
    constexpr int NCHUNK = K / 32;

    __shared__ __align__(16) uint16_t Ahi[128 * AS];
    __shared__ __align__(16) uint16_t Bhi[128 * AS];
    __shared__ float s_sum[128], s_sumsq[128];
    __shared__ float s_scale[256], s_shift[256];

    const int tid  = threadIdx.x;
    const int lane = tid & 31, wid = tid >> 5;
    const int bm = blockIdx.x * 128;
    const int bn = blockIdx.y * 128;
    const int wm = (wid >> 1) * 32;
    const int wn = (wid & 1) * 64;
    const int grp = lane >> 2, qid = lane & 3;

    if (MODE == 1 && tid < 128) { s_sum[tid] = 0.f; s_sumsq[tid] = 0.f; }
    if (MODE == 2) {   // fused bn_finalize: every CTA computes scale/shift
        float mean = (float)(g_sum[tid] / (double)NN);
        float var  = (float)(g_sumsq[tid] / (double)NN) - mean * mean;
        float sc = __ldg(&gam[tid]) * rsqrtf(var + 1e-5f);
        s_scale[tid] = sc;
        s_shift[tid] = fmaf(-mean, sc, __ldg(&bet[tid]));
        __syncthreads();
    }

    float acc[2][8][4];
#pragma unroll
    for (int mt = 0; mt < 2; mt++)
#pragma unroll
        for (int nt = 0; nt < 8; nt++)
#pragma unroll
            for (int q = 0; q < 4; q++) acc[mt][nt][q] = 0.f;

    const int arow = tid >> 1, ahalf = tid & 1;        // A loader: row, 16-col half
    const int bnid = tid & 127, bkh = (tid >> 7) * 16; // B loader: n col, 16-k half
    const int rA = bm + arow;

    auto loadA = [&](int k0, float* v) {
        if (rA < NN) {
            if (MODE == 2) {             // bf16 z read + BN + ReLU
                const uint32_t* zp = g_zb + ((size_t)rA * 256 + k0 + ahalf * 16) / 2;
                uint32_t u[8];
                *reinterpret_cast<uint4*>(u)     = __ldg(reinterpret_cast<const uint4*>(zp));
                *reinterpret_cast<uint4*>(u + 4) = __ldg(reinterpret_cast<const uint4*>(zp + 4));
                const int kb = k0 + ahalf * 16;
#pragma unroll
                for (int j = 0; j < 8; j++) {
                    v[2 * j + 0] = fmaxf(fmaf(bflo(u[j]), s_scale[kb + 2 * j],     s_shift[kb + 2 * j]), 0.f);
                    v[2 * j + 1] = fmaxf(fmaf(bfhi(u[j]), s_scale[kb + 2 * j + 1], s_shift[kb + 2 * j + 1]), 0.f);
                }
            } else if (MODE == 1) {      // bf16 agg read
                const uint32_t* ap = g_aggb + ((size_t)rA * 128 + k0 + ahalf * 16) / 2;
                uint32_t u[8];
                *reinterpret_cast<uint4*>(u)     = __ldg(reinterpret_cast<const uint4*>(ap));
                *reinterpret_cast<uint4*>(u + 4) = __ldg(reinterpret_cast<const uint4*>(ap + 4));
#pragma unroll
                for (int j = 0; j < 8; j++) {
                    v[2 * j + 0] = bflo(u[j]);
                    v[2 * j + 1] = bfhi(u[j]);
                }
            } else {                     // fp32 x read (MODE0)
                const float* ap = Aext + (size_t)rA * K + k0 + ahalf * 16;
#pragma unroll
                for (int q = 0; q < 4; q++)
                    *reinterpret_cast<float4*>(v + 4 * q) =
                        __ldg(reinterpret_cast<const float4*>(ap + 4 * q));
            }
        } else {
#pragma unroll
            for (int j = 0; j < 16; j++) v[j] = 0.f;
        }
    };
    auto loadB = [&](int k0, uint32_t* vb) {   // 16 bf16 = 8 uint32, preconverted
        const uint32_t* ph = reinterpret_cast<const uint32_t*>(BH) +
                             ((size_t)(bn + bnid) * K + k0 + bkh) / 2;
        *reinterpret_cast<uint4*>(vb)     = __ldg(reinterpret_cast<const uint4*>(ph));
        *reinterpret_cast<uint4*>(vb + 4) = __ldg(reinterpret_cast<const uint4*>(ph + 4));
    };
    auto storeA = [&](const float* v) {
#pragma unroll
        for (int q = 0; q < 2; q++) {
            uint32_t hs[4];
#pragma unroll
            for (int p = 0; p < 4; p++)
                hs[p] = cvt2(v[q * 8 + p * 2], v[q * 8 + p * 2 + 1]);
            const int c = ahalf * 16 + q * 8;
            *reinterpret_cast<uint4*>(&Ahi[arow * AS + c]) = make_uint4(hs[0], hs[1], hs[2], hs[3]);
        }
    };
    auto storeB = [&](const uint32_t* vb) {
        *reinterpret_cast<uint4*>(&Bhi[bnid * AS + bkh])     = *reinterpret_cast<const uint4*>(vb);
        *reinterpret_cast<uint4*>(&Bhi[bnid * AS + bkh + 8]) = *reinterpret_cast<const uint4*>(vb + 4);
    };
    auto mmaStep = [&]() {
#pragma unroll
        for (int s = 0; s < 32; s += 16) {
            uint32_t ah[2][4];
#pragma unroll
            for (int mt = 0; mt < 2; mt++) {
                const int r0 = (wm + mt * 16 + grp) * AS + s + qid * 2;
                const int r8 = r0 + 8 * AS;
                ah[mt][0] = *reinterpret_cast<const uint32_t*>(&Ahi[r0]);
                ah[mt][1] = *reinterpret_cast<const uint32_t*>(&Ahi[r8]);
                ah[mt][2] = *reinterpret_cast<const uint32_t*>(&Ahi[r0 + 8]);
                ah[mt][3] = *reinterpret_cast<const uint32_t*>(&Ahi[r8 + 8]);
            }
#pragma unroll
            for (int nt = 0; nt < 8; nt++) {
                const int nb = (wn + nt * 8 + grp) * AS + s + qid * 2;
                uint32_t bh[2];
                bh[0] = *reinterpret_cast<const uint32_t*>(&Bhi[nb]);
                bh[1] = *reinterpret_cast<const uint32_t*>(&Bhi[nb + 8]);
#pragma unroll
                for (int mt = 0; mt < 2; mt++)
                    mma16816(acc[mt][nt], ah[mt], bh);
            }
        }
    };

    // ---- prologue: chunk 0 ----
    {
        float va[16]; uint32_t vb[8];
        loadA(0, va); loadB(0, vb);
        storeA(va);   storeB(vb);
    }
    __syncthreads();

    // ---- pipelined main loop (two syncs, single buffer — proven) ----
    for (int ch = 0; ch < NCHUNK - 1; ch++) {
        float wa[16]; uint32_t wb[8];
        loadA((ch + 1) * 32, wa);
        loadB((ch + 1) * 32, wb);
        mmaStep();
        __syncthreads();
        storeA(wa); storeB(wb);
        __syncthreads();
    }
    mmaStep();

    // ---- epilogue: bias / residual / ReLU -> bf16 outputs (+ BN stats) ----
#pragma unroll
    for (int nt = 0; nt < 8; nt++) {
        const int ccl = wn + nt * 8 + qid * 2;
        const int cc  = bn + ccl;
        const float b0 = bias[cc], b1 = bias[cc + 1];
        float cs0 = 0.f, cs1 = 0.f, cq0 = 0.f, cq1 = 0.f;
#pragma unroll
        for (int mt = 0; mt < 2; mt++) {
            const int r0 = bm + wm + mt * 16 + grp;
#pragma unroll
            for (int hrow = 0; hrow < 2; hrow++) {
                const int r = r0 + hrow * 8;
                if (r < NN) {
                    float2 o;
                    o.x = acc[mt][nt][hrow * 2 + 0] + b0;
                    o.y = acc[mt][nt][hrow * 2 + 1] + b1;
                    if (MODE == 2) {     // residual from bf16 h
                        uint32_t hu = g_hb[((size_t)r * 128 + cc) >> 1];
                        o.x = fmaxf(o.x + bflo(hu), 0.f);
                        o.y = fmaxf(o.y + bfhi(hu), 0.f);
                    }
                    if (MODE == 1) {
                        cs0 += o.x; cq0 = fmaf(o.x, o.x, cq0);
                        cs1 += o.y; cq1 = fmaf(o.y, o.y, cq1);
                        g_zb[((size_t)r * 256 + cc) >> 1] = cvt2(o.x, o.y);
                    } else {
                        g_hb[((size_t)r * 128 + cc) >> 1] = cvt2(o.x, o.y);
                    }
                }
            }
        }
        if (MODE == 1) {
            atomicAdd(&s_sum[ccl],       cs0);
            atomicAdd(&s_sum[ccl + 1],   cs1);
            atomicAdd(&s_sumsq[ccl],     cq0);
            atomicAdd(&s_sumsq[ccl + 1], cq1);
        }
    }
    if (MODE == 1) {
        __syncthreads();
        if (tid < 128) {
            atomicAdd(&g_sum[bn + tid],   (double)s_sum[tid]);
            atomicAdd(&g_sumsq[bn + tid], (double)s_sumsq[tid]);
        }
    }
}

// ---------------- small utility kernels -----------------------------------
__global__ void zero_pool_kernel() {
    int i = blockIdx.x * 256 + threadIdx.x;
    g_pool[i] = 0.f;
    if (i < 2 * GG) g_cnt[i] = 0.f;
}

// g_aggb = bf16( (1+eps) * hb ); block 0 zeroes BN accumulators.
__global__ void init_agg_kernel(const float* __restrict__ eps) {
    int i = blockIdx.x * 256 + threadIdx.x;   // 6250 x 256, 4 uint32 (8 vals) each
    if (blockIdx.x == 0) { g_sum[threadIdx.x] = 0.0; g_sumsq[threadIdx.x] = 0.0; }
    float e = 1.0f + __ldg(eps);
    uint4 v = *reinterpret_cast<const uint4*>(&g_hb[i * 4]);
    uint4 o;
    o.x = cvt2(e * bflo(v.x), e * bfhi(v.x));
    o.y = cvt2(e * bflo(v.y), e * bfhi(v.y));
    o.z = cvt2(e * bflo(v.z), e * bfhi(v.z));
    o.w = cvt2(e * bflo(v.w), e * bfhi(v.w));
    *reinterpret_cast<uint4*>(&g_aggb[i * 4]) = o;
}

// 16 threads per edge: gather 16B bf16, one v4.bf16x2 red (16B) into aggb[dst]
__global__ void scatter_kernel(const int* __restrict__ ei) {
    int idx = blockIdx.x * 256 + threadIdx.x;  // grid 100000 x 256 (== E*16)
    int e = idx >> 4;
    int c = idx & 15;
    int src = __ldg(&ei[e]);
    int dst = __ldg(&ei[EE + e]);
    uint4 v = *reinterpret_cast<const uint4*>(&g_hb[src * 64 + c * 4]);
    uint32_t* p = &g_aggb[dst * 64 + c * 4];
    asm volatile("red.global.add.noftz.v4.bf16x2 [%0], {%1,%2,%3,%4};"
                 :: "l"(p), "r"(v.x), "r"(v.y), "r"(v.z), "r"(v.w) : "memory");
}

__global__ void pool_kernel(const int* __restrict__ batch, int which) {
    int idx = blockIdx.x * 256 + threadIdx.x;   // 12500 x 256 (== N*32)
    int n = idx >> 5;
    int c = idx & 31;
    int g = __ldg(&batch[n]);
    uint2 v = *reinterpret_cast<const uint2*>(&g_hb[n * 64 + c * 2]);
    float f0 = bflo(v.x), f1 = bfhi(v.x), f2 = bflo(v.y), f3 = bfhi(v.y);
    float* p = &g_pool[(which * GG + g) * 128 + c * 4];
    asm volatile("red.global.add.v4.f32 [%0], {%1,%2,%3,%4};"
                 :: "l"(p), "f"(f0), "f"(f1), "f"(f2), "f"(f3) : "memory");
    if ((idx & 31) == 0) atomicAdd(&g_cnt[which * GG + g], 1.0f);
}

__global__ void head1_kernel(const float* __restrict__ W, const float* __restrict__ b) {
    int g = blockIdx.x, j = threadIdx.x;   // 64 x 256
    __shared__ float xc[256];
    if (j < 128) xc[j] = g_pool[g * 128 + j] / fmaxf(g_cnt[g], 1.0f);
    else         xc[j] = g_pool[(GG + g) * 128 + (j - 128)] / fmaxf(g_cnt[GG + g], 1.0f);
    __syncthreads();
    float acc = b[j];
#pragma unroll 8
    for (int k = 0; k < 256; k++) acc = fmaf(xc[k], W[k * 256 + j], acc);
    g_fc1o[g * 256 + j] = fmaxf(acc, 0.f);
}

__global__ void head2_kernel(const float* __restrict__ W, const float* __restrict__ b) {
    int g = blockIdx.x, j = threadIdx.x;   // 64 x 64
    __shared__ float xin[256];
    for (int k = j; k < 256; k += 64) xin[k] = g_fc1o[g * 256 + k];
    __syncthreads();
    float acc = b[j];
#pragma unroll 8
    for (int k = 0; k < 256; k++) acc = fmaf(xin[k], W[k * 64 + j], acc);
    g_fc2o[g * 64 + j] = fmaxf(acc, 0.f);
}

__global__ void head3_kernel(const float* __restrict__ W, const float* __restrict__ b,
                             float* __restrict__ out) {
    int g = threadIdx.x;   // 1 x 64
    float acc = b[0];
#pragma unroll
    for (int k = 0; k < 64; k++) acc = fmaf(g_fc2o[g * 64 + k], W[k], acc);
    out[g] = 1.0f / (1.0f + expf(-acc));
}

// ---------------- orchestration -------------------------------------------
extern "C" void kernel_launch(void* const* d_in, const int* in_sizes, int n_in,
                              void* d_out, int out_size) {
    const float* x[2]     = { (const float*)d_in[0], (const float*)d_in[3] };
    const int*   ei[2]    = { (const int*)d_in[1],   (const int*)d_in[4] };
    const int*   batch[2] = { (const int*)d_in[2],   (const int*)d_in[5] };

    uint16_t *eB, *w1B, *w2B;
    cudaGetSymbolAddress((void**)&eB, g_eB);
    cudaGetSymbolAddress((void**)&w1B, g_w1B);
    cudaGetSymbolAddress((void**)&w2B, g_w2B);

    const int GRID_M = (NN + 127) / 128;   // 782

    zero_pool_kernel<<<64, 256>>>();

    for (int b = 0; b < 2; b++) {
        int o = 6 + b * 9;
        const float* embW = (const float*)d_in[o + 0];
        const float* embB = (const float*)d_in[o + 1];
        const float* W1   = (const float*)d_in[o + 2];
        const float* b1   = (const float*)d_in[o + 3];
        const float* gam  = (const float*)d_in[o + 4];
        const float* bet  = (const float*)d_in[o + 5];
        const float* W2   = (const float*)d_in[o + 6];
        const float* b2   = (const float*)d_in[o + 7];
        const float* eps  = (const float*)d_in[o + 8];

        // pre-convert this branch's weights to [n][k] bf16
        convB_kernel<<<dim3(256, 1), 256>>>(embW, eB, 1024, 128);
        convB_kernel<<<dim3(64, 4), 256>>>(W1, w1B, 128, 256);
        convB_kernel<<<dim3(64, 4), 256>>>(W2, w2B, 256, 128);

        mma_gemm<0><<<dim3(GRID_M, 1), 256>>>(x[b], eB, embB, nullptr, nullptr);

        for (int i = 0; i < 4; i++) {
            init_agg_kernel<<<6250, 256>>>(eps + i);
            scatter_kernel<<<100000, 256>>>(ei[b]);
            mma_gemm<1><<<dim3(GRID_M, 2), 256>>>(nullptr, w1B + (size_t)i * 256 * 128,
                                                  b1 + i * 256, nullptr, nullptr);
            mma_gemm<2><<<dim3(GRID_M, 1), 256>>>(nullptr, w2B + (size_t)i * 128 * 256,
                                                  b2 + i * 128, gam + i * 256, bet + i * 256);
        }
        pool_kernel<<<12500, 256>>>(batch[b], b);
    }

    head1_kernel<<<64, 256>>>((const float*)d_in[24], (const float*)d_in[25]);
    head2_kernel<<<64, 64>>>((const float*)d_in[26], (const float*)d_in[27]);
    head3_kernel<<<1, 64>>>((const float*)d_in[28], (const float*)d_in[29], (float*)d_out);
}